// round 3
// baseline (speedup 1.0000x reference)
#include <cuda_runtime.h>
#include <cstdint>

// HarmonicPolynomialR3Generator — R3: 4-way k-split for occupancy.
//  - f32x2 packs 2 points (lanes): slot s handles points (base+s, base+56+s).
//  - 4 threads per slot: thread j computes outputs k ≡ j (mod 4) of each stage.
//    prev vector exchanged via per-slot smem ping-pong (ull pairs), __syncwarp.
//  - cob in smem as duplicated (v,v) pairs, row-major per output-k, row stride
//    even + bank-staggered so the 4 j-rows hit disjoint bank quads.
//  - outputs staged in smem tile [112 pts][121 f32], one cp.async.bulk per CTA.
//  - 109.3KB smem/CTA, 224 thr, 2 CTAs/SM -> 14 warps/SM (was 4).

typedef unsigned long long ull;

__device__ __forceinline__ ull ffma2(ull a, ull b, ull c) {
    ull d; asm("fma.rn.f32x2 %0, %1, %2, %3;" : "=l"(d) : "l"(a), "l"(b), "l"(c)); return d;
}
__device__ __forceinline__ ull fmul2(ull a, ull b) {
    ull d; asm("mul.rn.f32x2 %0, %1, %2;" : "=l"(d) : "l"(a), "l"(b)); return d;
}
__device__ __forceinline__ ull pack2(float lo, float hi) {
    ull d; asm("mov.b64 %0, {%1, %2};" : "=l"(d) : "f"(lo), "f"(hi)); return d;
}
__device__ __forceinline__ void st2s(float* a, float* b, ull v) {
    float lo, hi; asm("mov.b64 {%0, %1}, %2;" : "=f"(lo), "=f"(hi) : "l"(v));
    *a = lo; *b = hi;
}
__device__ __forceinline__ uint32_t smem_u32(const void* p) {
    uint32_t a;
    asm("{ .reg .u64 t; cvta.to.shared.u64 t, %1; cvt.u32.u64 %0, t; }" : "=r"(a) : "l"(p));
    return a;
}

#define BLOCK 224
#define SLOTS 56
#define TILE  112

// cob smem layout (ull units): cob1 at 0 (9, pad 10); stage l at OFFl,
// row-major [NK][RS], RS even & bank-staggered.
#define OFF2   10   // PL=3,  RS=10, NK=5
#define OFF3   60   // PL=5,  RS=18, NK=7
#define OFF4   186  // PL=7,  RS=22, NK=9
#define OFF5   384  // PL=9,  RS=28, NK=11
#define OFF6   692  // PL=11, RS=34, NK=13
#define OFF7   1134 // PL=13, RS=42, NK=15
#define OFF8   1764 // PL=15, RS=46, NK=17
#define OFF9   2546 // PL=17, RS=52, NK=19
#define OFF10  3534 // PL=19, RS=58, NK=21
#define COB_ULL 4752
#define EX_ULL  (SLOTS * 44)           // ping-pong: 2 x 22 per slot
#define BUF_FLOATS (TILE * 121)
#define SMEM_BYTES ((COB_ULL + EX_ULL) * 8 + BUF_FLOATS * 4)  // 111936

// Load cob_l (global row-major [NK][3PL]) -> smem rows stride RS, dup pairs, zero pad.
template <int PL, int RS>
__device__ __forceinline__ void load_cob(const float* __restrict__ c, ull* __restrict__ dst, int tid) {
    constexpr int NK = PL + 2;
    constexpr int M = 3 * PL;
    for (int e = tid; e < NK * RS; e += BLOCK) {
        int k = e / RS;
        int m = e - k * RS;
        float v = (m < M) ? c[k * M + m] : 0.0f;
        dst[e] = pack2(v, v);
    }
}

// One stage: prev (PL packed values) read from exin; thread j computes
// k = j, j+4, ...; writes exout[k] + unpacked buffer.
template <int PL, int RS>
__device__ __forceinline__ void stageB(const ull* __restrict__ cb, const int j,
                                       const ull f1x, const ull f1y, const ull f1z,
                                       const ull* __restrict__ exin, ull* __restrict__ exout,
                                       float* __restrict__ b0, float* __restrict__ b1) {
    constexpr int NK = PL + 2;
    constexpr int TM = (NK + 3) >> 2;
    __syncwarp();                       // prior stage's exchange writes -> visible
    ull prev[PL];
#pragma unroll
    for (int i = 0; i < PL; ++i) prev[i] = exin[i];
#pragma unroll
    for (int t = 0; t < TM; ++t) {
        const int k = j + 4 * t;
        const int kc = (k < NK) ? k : (NK - 1);   // clamp (padding lanes)
        const ull* row = cb + kc * RS;
        ull a0, a1, a2;
        {   // m = 0,1 (pair) and m = 2 handled below in the generic loop by init flags
            ulonglong2 v = *reinterpret_cast<const ulonglong2*>(row);
            a0 = fmul2(v.x, prev[0]);
            a1 = fmul2(v.y, prev[0]);
        }
        {
            ulonglong2 v = *reinterpret_cast<const ulonglong2*>(row + 2);
            a2 = fmul2(v.x, prev[0]);                 // m=2: i=0,c=2
            a0 = ffma2(v.y, prev[1], a0);             // m=3: i=1,c=0
        }
#pragma unroll
        for (int p = 2; p < (3 * PL - 1) / 2; ++p) {  // pairs m = 2p, 2p+1
            ulonglong2 v = *reinterpret_cast<const ulonglong2*>(row + 2 * p);
            const int m0 = 2 * p, m1 = 2 * p + 1;
            const int i0 = m0 / 3, c0 = m0 % 3;
            const int i1 = m1 / 3, c1 = m1 % 3;
            ull pa = prev[i0], pb = prev[i1];
            if (c0 == 0) a0 = ffma2(v.x, pa, a0); else if (c0 == 1) a1 = ffma2(v.x, pa, a1); else a2 = ffma2(v.x, pa, a2);
            if (c1 == 0) a0 = ffma2(v.y, pb, a0); else if (c1 == 1) a1 = ffma2(v.y, pb, a1); else a2 = ffma2(v.y, pb, a2);
        }
        {   // tail m = 3PL-1: i = PL-1, c = (3PL-1)%3 = 2
            a2 = ffma2(row[3 * PL - 1], prev[PL - 1], a2);
        }
        ull r = ffma2(a0, f1x, ffma2(a1, f1y, fmul2(a2, f1z)));
        if (k < NK) {
            exout[k] = r;
            st2s(b0 + k, b1 + k, r);
        }
    }
}

__global__ void __launch_bounds__(BLOCK, 2)
harmonic_kernel(const float* __restrict__ pts,
                const float* __restrict__ c1, const float* __restrict__ c2,
                const float* __restrict__ c3, const float* __restrict__ c4,
                const float* __restrict__ c5, const float* __restrict__ c6,
                const float* __restrict__ c7, const float* __restrict__ c8,
                const float* __restrict__ c9, const float* __restrict__ c10,
                float* __restrict__ out, int N) {
    extern __shared__ ull dyns[];
    ull* scob = dyns;
    ull* ex = dyns + COB_ULL;
    float* buf = reinterpret_cast<float*>(dyns + COB_ULL + EX_ULL);

    const int tid = threadIdx.x;
    const int slot = tid >> 2;
    const int j = tid & 3;

    if (tid < 9) { float v = c1[tid]; scob[tid] = pack2(v, v); }
    load_cob<3, 10>(c2, scob + OFF2, tid);
    load_cob<5, 18>(c3, scob + OFF3, tid);
    load_cob<7, 22>(c4, scob + OFF4, tid);
    load_cob<9, 28>(c5, scob + OFF5, tid);
    load_cob<11, 34>(c6, scob + OFF6, tid);
    load_cob<13, 42>(c7, scob + OFF7, tid);
    load_cob<15, 46>(c8, scob + OFF8, tid);
    load_cob<17, 52>(c9, scob + OFF9, tid);
    load_cob<19, 58>(c10, scob + OFF10, tid);
    __syncthreads();

    const int base = blockIdx.x * TILE;
    int rem = N - base; if (rem > TILE) rem = TILE;
    const int lo = base + slot;
    const int hi = lo + SLOTS;

    float ax = 0.f, ay = 0.f, az = 0.f, bx = 0.f, by = 0.f, bz = 0.f;
    if (lo < N) { ax = pts[3 * lo]; ay = pts[3 * lo + 1]; az = pts[3 * lo + 2]; }
    if (hi < N) { bx = pts[3 * hi]; by = pts[3 * hi + 1]; bz = pts[3 * hi + 2]; }
    ull px = pack2(ax, bx), py = pack2(ay, by), pz = pack2(az, bz);

    ull f1x = ffma2(scob[0], px, ffma2(scob[1], py, fmul2(scob[2], pz)));
    ull f1y = ffma2(scob[3], px, ffma2(scob[4], py, fmul2(scob[5], pz)));
    ull f1z = ffma2(scob[6], px, ffma2(scob[7], py, fmul2(scob[8], pz)));

    ull* exA = ex + slot * 44;
    ull* exB = exA + 22;
    float* b0 = buf + slot * 121;
    float* b1 = b0 + SLOTS * 121;

    if (j == 0) {
        b0[0] = 1.0f; b1[0] = 1.0f;
        st2s(b0 + 1, b1 + 1, f1x);
        st2s(b0 + 2, b1 + 2, f1y);
        st2s(b0 + 3, b1 + 3, f1z);
        exA[0] = f1x; exA[1] = f1y; exA[2] = f1z;
    }

    stageB<3, 10>(scob + OFF2, j, f1x, f1y, f1z, exA, exB, b0 + 4, b1 + 4);     // l=2
    stageB<5, 18>(scob + OFF3, j, f1x, f1y, f1z, exB, exA, b0 + 9, b1 + 9);     // l=3
    stageB<7, 22>(scob + OFF4, j, f1x, f1y, f1z, exA, exB, b0 + 16, b1 + 16);   // l=4
    stageB<9, 28>(scob + OFF5, j, f1x, f1y, f1z, exB, exA, b0 + 25, b1 + 25);   // l=5
    stageB<11, 34>(scob + OFF6, j, f1x, f1y, f1z, exA, exB, b0 + 36, b1 + 36);  // l=6
    stageB<13, 42>(scob + OFF7, j, f1x, f1y, f1z, exB, exA, b0 + 49, b1 + 49);  // l=7
    stageB<15, 46>(scob + OFF8, j, f1x, f1y, f1z, exA, exB, b0 + 64, b1 + 64);  // l=8
    stageB<17, 52>(scob + OFF9, j, f1x, f1y, f1z, exB, exA, b0 + 81, b1 + 81);  // l=9
    stageB<19, 58>(scob + OFF10, j, f1x, f1y, f1z, exA, exB, b0 + 100, b1 + 100); // l=10

    __syncthreads();
    asm volatile("fence.proxy.async.shared::cta;" ::: "memory");

    const unsigned bytes = (unsigned)rem * 121u * 4u;
    const unsigned mainb = bytes & ~15u;
    float* gdst = out + (size_t)base * 121;
    if (tid == 0 && mainb) {
        uint32_t saddr = smem_u32(buf);
        asm volatile("cp.async.bulk.global.shared::cta.bulk_group [%0], [%1], %2;"
                     :: "l"(gdst), "r"(saddr), "r"(mainb) : "memory");
        asm volatile("cp.async.bulk.commit_group;" ::: "memory");
    }
    for (int e = (int)(mainb >> 2) + tid; e < rem * 121; e += BLOCK)
        gdst[e] = buf[e];
    if (tid == 0 && mainb)
        asm volatile("cp.async.bulk.wait_group 0;" ::: "memory");
}

extern "C" void kernel_launch(void* const* d_in, const int* in_sizes, int n_in,
                              void* d_out, int out_size) {
    const float* points = (const float*)d_in[0];
    const int N = in_sizes[0] / 3;
    float* out = (float*)d_out;

    cudaFuncSetAttribute(harmonic_kernel,
                         cudaFuncAttributeMaxDynamicSharedMemorySize, SMEM_BYTES);

    const int grid = (N + TILE - 1) / TILE;
    harmonic_kernel<<<grid, BLOCK, SMEM_BYTES>>>(
        points,
        (const float*)d_in[1], (const float*)d_in[2], (const float*)d_in[3],
        (const float*)d_in[4], (const float*)d_in[5], (const float*)d_in[6],
        (const float*)d_in[7], (const float*)d_in[8], (const float*)d_in[9],
        (const float*)d_in[10],
        out, N);
}